// round 4
// baseline (speedup 1.0000x reference)
#include <cuda_runtime.h>
#include <math.h>

// ---------------- problem constants ----------------
#define NPIX   262144            // 512*512 pixels per image
#define NIMG   64
#define NIC    128               // image-channels: [0,64)=region, [64,128)=affinity
#define NSAMP  16384             // every 16th pixel sampled (as 8-bit code)
#define POS_THR 0.1f
#define FALLBACK_POS 1000.0f
#define QSTEP  (1.1f / 255.0f)   // code step in sqrt(value) space
#define QSCALE (255.0f / 1.1f)

// ---------------- persistent-kernel geometry ----------------
#define NBLK     148             // <= SM count (GB300 has 152); all co-resident
#define NTH      1024
#define CHUNK_PX 16384           // pixels per chunk (one img, both channels)
#define NCHUNK   1024            // total pixel-chunks (16 per image)
#define MAXCH    7               // max chunks per block: 136*7 + 12*6 = 1024
#define SMEM_BYTES (MAXCH * 2 * CHUNK_PX)   // 229376 B < 227KB opt-in limit

// ---------------- device state (static, allocation-free) ----------------
__device__ __align__(4) unsigned char g_scode[NIC * NSAMP]; // 2MB code samples
__device__ float g_p[NIC];      // positive count (exact integer-valued)
__device__ float g_ps[NIC];     // sum of loss over positives
__device__ float g_ts[NIC];     // total loss sum
__device__ float g_C[NIC];      // count of codes > c_t
__device__ float g_S2[NIC];     // sum of code^2 over codes > c_t
__device__ int   g_ct[NIC];     // code threshold per image-channel
__device__ unsigned g_bar[4];   // grid barrier counters (zeroed per launch)

// ---------------- helpers ----------------
__device__ __forceinline__ float warp_sum(float v) {
    #pragma unroll
    for (int o = 16; o; o >>= 1) v += __shfl_xor_sync(0xffffffffu, v, o);
    return v;
}
__device__ __forceinline__ unsigned warp_sum_u(unsigned v) {
    #pragma unroll
    for (int o = 16; o; o >>= 1) v += __shfl_xor_sync(0xffffffffu, v, o);
    return v;
}
__device__ __forceinline__ void bar_arrive(int i) {
    __syncthreads();
    __threadfence();
    if (threadIdx.x == 0) atomicAdd(&g_bar[i], 1u);
}
__device__ __forceinline__ void bar_spin(int i) {
    if (threadIdx.x == 0) {
        while (*(volatile unsigned*)&g_bar[i] < NBLK) { }
    }
    __syncthreads();
    __threadfence();
}

// ---------------- k0: zero per-launch state ----------------
__global__ void k0_zero() {
    int i = threadIdx.x;
    if (i < NIC) {
        g_p[i] = 0.f; g_ps[i] = 0.f; g_ts[i] = 0.f;
        g_C[i] = 0.f; g_S2[i] = 0.f;
    }
    if (i >= NIC && i < NIC + 4) g_bar[i - NIC] = 0u;
}

// ---------------- persistent kernel ----------------
__global__ void __launch_bounds__(NTH, 1) k_main(
    const float* __restrict__ rlab, const float* __restrict__ alab,
    const float* __restrict__ rpre, const float* __restrict__ apre,
    const float* __restrict__ mask, const int* __restrict__ neg_rto,
    float* __restrict__ out)
{
    extern __shared__ unsigned char sm_codes[];
    const int b   = blockIdx.x;
    const int tid = threadIdx.x;
    const int ln  = tid & 31;

    const int nch = (b < 136) ? 7 : 6;
    const int c0  = (b < 136) ? 7 * b : 952 + 6 * (b - 136);

    // ================= Pass 1: stream inputs -> stats + smem codes =================
    for (int s = 0; s < nch; ++s) {
        const int c    = c0 + s;
        const int img  = c >> 4;
        const int pxb  = (c & 15) << 14;   // * CHUNK_PX
        const size_t off0 = (size_t)img * NPIX + pxb;
        unsigned* __restrict__ codR = (unsigned*)(sm_codes + s * 2 * CHUNK_PX);
        unsigned* __restrict__ codA = (unsigned*)(sm_codes + s * 2 * CHUNK_PX + CHUNK_PX);

        float p_r = 0.f, ps_r = 0.f, ts_r = 0.f;
        float p_a = 0.f, ps_a = 0.f, ts_a = 0.f;

        #pragma unroll 2
        for (int it = 0; it < CHUNK_PX / (NTH * 4); ++it) {   // 4 iterations
            const int px = it * (NTH * 4) + tid * 4;
            const size_t off = off0 + (size_t)px;

            float4 rl = __ldcs((const float4*)(rlab + off));
            float4 rp = __ldcs((const float4*)(rpre + off));
            float4 al = __ldcs((const float4*)(alab + off));
            float4 ap = __ldcs((const float4*)(apre + off));
            float4 mk = __ldcs((const float4*)(mask + off));

            int cr[4], ca[4];
            #define PROC(L, P, M, PC, PS, TS, CODE)                    \
            {   float d = (P) - (L);                                   \
                float l = d * d * (M);                                 \
                TS += l;                                               \
                bool po = (L) > POS_THR;                               \
                PC += po ? 1.f : 0.f;                                  \
                PS += po ? l   : 0.f;                                  \
                float nv = po ? 0.f : l;                               \
                int cc = __float2int_rn(sqrtf(nv) * QSCALE);           \
                CODE = min(cc, 255); }

            PROC(rl.x, rp.x, mk.x, p_r, ps_r, ts_r, cr[0])
            PROC(rl.y, rp.y, mk.y, p_r, ps_r, ts_r, cr[1])
            PROC(rl.z, rp.z, mk.z, p_r, ps_r, ts_r, cr[2])
            PROC(rl.w, rp.w, mk.w, p_r, ps_r, ts_r, cr[3])
            PROC(al.x, ap.x, mk.x, p_a, ps_a, ts_a, ca[0])
            PROC(al.y, ap.y, mk.y, p_a, ps_a, ts_a, ca[1])
            PROC(al.z, ap.z, mk.z, p_a, ps_a, ts_a, ca[2])
            PROC(al.w, ap.w, mk.w, p_a, ps_a, ts_a, ca[3])
            #undef PROC

            codR[px >> 2] = (unsigned)cr[0] | ((unsigned)cr[1] << 8) |
                            ((unsigned)cr[2] << 16) | ((unsigned)cr[3] << 24);
            codA[px >> 2] = (unsigned)ca[0] | ((unsigned)ca[1] << 8) |
                            ((unsigned)ca[2] << 16) | ((unsigned)ca[3] << 24);

            if ((px & 15) == 0) {          // every 16th pixel -> sample
                const int gpx = pxb + px;
                g_scode[img * NSAMP + (gpx >> 4)]          = (unsigned char)cr[0];
                g_scode[(NIMG + img) * NSAMP + (gpx >> 4)] = (unsigned char)ca[0];
            }
        }

        // warp-level stat reduction -> global atomics (REDG, no block sync needed)
        float v;
        v = warp_sum(p_r);  if (ln == 0) atomicAdd(&g_p [img], v);
        v = warp_sum(ps_r); if (ln == 0) atomicAdd(&g_ps[img], v);
        v = warp_sum(ts_r); if (ln == 0) atomicAdd(&g_ts[img], v);
        v = warp_sum(p_a);  if (ln == 0) atomicAdd(&g_p [NIMG + img], v);
        v = warp_sum(ps_a); if (ln == 0) atomicAdd(&g_ps[NIMG + img], v);
        v = warp_sum(ts_a); if (ln == 0) atomicAdd(&g_ts[NIMG + img], v);
    }

    bar_arrive(0);
    bar_spin(0);

    // ================= Stage 2: per-IC code threshold (blocks 0..127) =================
    __shared__ int s_lo, s_hi;
    __shared__ unsigned s_cnt[NTH / 32];
    if (b < NIC) {
        const int ic = b;
        unsigned sv[NSAMP / 4 / NTH];   // 4 x u32 = 16 sample codes
        const unsigned* sp = ((const unsigned*)g_scode) + ic * (NSAMP / 4);
        #pragma unroll
        for (int i = 0; i < NSAMP / 4 / NTH; ++i)
            sv[i] = sp[tid + NTH * i];

        const float p    = g_p[ic];
        const float peff = (p > 0.f) ? p : FALLBACK_POS;
        const float kf   = (float)(*neg_rto) * peff;
        int k = (int)floorf(kf);
        int j = k >> 4;                 // sample rank (NPIX/NSAMP = 16)
        if (j < 0) j = 0;
        if (j > NSAMP - 1) j = NSAMP - 1;

        if (tid == 0) { s_lo = -1; s_hi = 255; }
        __syncthreads();

        for (int iter = 0; iter < 8; ++iter) {
            const int mid = (s_lo + s_hi) >> 1;
            const unsigned mid4 = (unsigned)mid * 0x01010101u;
            unsigned cc = 0;
            #pragma unroll
            for (int i = 0; i < NSAMP / 4 / NTH; ++i) {
                unsigned m = __vcmpgtu4(sv[i], mid4);
                cc = __dp4a(m & 0x01010101u, 0x01010101u, cc);
            }
            cc = warp_sum_u(cc);
            if (ln == 0) s_cnt[tid >> 5] = cc;
            __syncthreads();
            if (tid == 0) {
                unsigned tot = 0;
                #pragma unroll
                for (int i = 0; i < NTH / 32; ++i) tot += s_cnt[i];
                if ((int)tot > j) s_lo = mid; else s_hi = mid;
            }
            __syncthreads();
        }
        if (tid == 0) g_ct[ic] = s_hi;
    }

    bar_arrive(1);
    bar_spin(1);

    // ================= Stage 3: exact C, sum(code^2) over smem codes =================
    for (int s = 0; s < nch; ++s) {
        const int c   = c0 + s;
        const int img = c >> 4;
        #pragma unroll
        for (int ch = 0; ch < 2; ++ch) {
            const int ic = img + ch * NIMG;
            const unsigned ct4 = (unsigned)g_ct[ic] * 0x01010101u;
            const uint4* base = (const uint4*)(sm_codes + s * 2 * CHUNK_PX + ch * CHUNK_PX);
            uint4 wv = base[tid];   // 16 KB / 1024 threads = one uint4 each
            unsigned cnt = 0, sc2 = 0;
            #define STEP(x)                                        \
            {   unsigned m  = __vcmpgtu4((x), ct4);                \
                unsigned sl = (x) & m;                             \
                sc2 = __dp4a(sl, sl, sc2);                         \
                cnt = __dp4a(m & 0x01010101u, 0x01010101u, cnt); }
            STEP(wv.x) STEP(wv.y) STEP(wv.z) STEP(wv.w)
            #undef STEP
            cnt = warp_sum_u(cnt);
            sc2 = warp_sum_u(sc2);
            if (ln == 0) {
                atomicAdd(&g_C[ic],  (float)cnt);
                atomicAdd(&g_S2[ic], (float)sc2);
            }
        }
    }

    bar_arrive(2);

    // ================= Final: block 0 assembles the scalar =================
    if (b == 0) {
        bar_spin(2);
        float v = 0.f;
        if (tid < NIC) {
            const int ic = tid;
            const float p  = g_p[ic];
            const float ps = g_ps[ic];
            const float ts = g_ts[ic];
            const float C  = g_C[ic];
            const float S2 = g_S2[ic];
            const float ct = (float)g_ct[ic];
            const float n  = (float)NPIX - p;

            const float pos_loss = (p > 0.f) ? ps / fmaxf(p, 1.f) : 0.f;
            const float peff = (p > 0.f) ? p : FALLBACK_POS;
            const float kf   = (float)(*neg_rto) * peff;
            const float k    = floorf(kf);

            const float S    = S2 * (QSTEP * QSTEP);
            const float tval = (ct * QSTEP) * (ct * QSTEP);

            float neg_loss;
            if ((p > 0.f) && (n < kf)) {
                neg_loss = (ts - ps) / fmaxf(n, 1.f);
            } else {
                neg_loss = (S + (k - C) * tval) / kf;
            }
            v = pos_loss + neg_loss;
        }
        float* red = (float*)sm_codes;   // reuse smem
        if (tid < NIC) red[tid] = v;
        __syncthreads();
        if (tid == 0) {
            float tot = 0.f;
            #pragma unroll
            for (int i = 0; i < NIC; ++i) tot += red[i];
            out[0] = tot / (float)NIMG;
        }
    }
}

// ---------------- launch ----------------
extern "C" void kernel_launch(void* const* d_in, const int* in_sizes, int n_in,
                              void* d_out, int out_size)
{
    const float* rlab = (const float*)d_in[0];
    const float* alab = (const float*)d_in[1];
    const float* rpre = (const float*)d_in[2];
    const float* apre = (const float*)d_in[3];
    const float* mask = (const float*)d_in[4];
    const int*   nrto = (const int*)  d_in[5];
    float* out = (float*)d_out;
    (void)in_sizes; (void)n_in; (void)out_size;

    cudaFuncSetAttribute(k_main, cudaFuncAttributeMaxDynamicSharedMemorySize, SMEM_BYTES);

    k0_zero<<<1, NIC + 4>>>();
    k_main <<<NBLK, NTH, SMEM_BYTES>>>(rlab, alab, rpre, apre, mask, nrto, out);
}

// round 5
// speedup vs baseline: 1.5036x; 1.5036x over previous
#include <cuda_runtime.h>
#include <math.h>

// ---------------- problem constants ----------------
#define NPIX   262144            // 512*512 pixels per image
#define NIMG   64
#define NIC    128               // image-channels: [0,64)=region, [64,128)=affinity
#define NSAMP  16384             // every 16th pixel sampled (as 8-bit code)
#define K1_BPI 32                // blocks per image in k1
#define K1_CHUNK (NPIX / K1_BPI) // 8192 pixels per block
#define K3_BPC 16                // blocks per image-channel in k3
#define NTHREADS 256
#define POS_THR 0.1f
#define FALLBACK_POS 1000.0f
#define QSTEP  (1.1f / 255.0f)   // code step in sqrt(value) space
#define QSCALE (255.0f / 1.1f)

// ---------------- device scratch (static, zero-initialized, allocation-free) ----
__device__ __align__(16) unsigned g_code[(size_t)NIC * NPIX / 4]; // 33.5MB packed codes
__device__ __align__(4) unsigned char g_scode[NIC * NSAMP];       // 2MB code samples
__device__ float g_p[NIC];      // positive count (exact integer-valued)
__device__ float g_ps[NIC];     // sum of loss over positives
__device__ float g_ts[NIC];     // total loss sum
__device__ float g_C[NIC];      // count of codes > c_t
__device__ float g_S2[NIC];     // sum of code^2 over codes > c_t
__device__ int   g_ct[NIC];     // code threshold per image-channel

// ---------------- helpers ----------------
__device__ __forceinline__ float warp_sum(float v) {
    #pragma unroll
    for (int o = 16; o; o >>= 1) v += __shfl_xor_sync(0xffffffffu, v, o);
    return v;
}
__device__ __forceinline__ unsigned warp_sum_u(unsigned v) {
    #pragma unroll
    for (int o = 16; o; o >>= 1) v += __shfl_xor_sync(0xffffffffu, v, o);
    return v;
}

// ---------------- k1: main input scan -> stats + 8-bit codes ----------------
__global__ void __launch_bounds__(NTHREADS) k1_scan(
    const float* __restrict__ rlab, const float* __restrict__ alab,
    const float* __restrict__ rpre, const float* __restrict__ apre,
    const float* __restrict__ mask)
{
    const int blk   = blockIdx.x;
    const int img   = blk / K1_BPI;
    const int chunk = blk % K1_BPI;
    const size_t ibase = (size_t)img * NPIX;
    const int pbase = chunk * K1_CHUNK;

    float p_r = 0.f, ps_r = 0.f, ts_r = 0.f;
    float p_a = 0.f, ps_a = 0.f, ts_a = 0.f;

    unsigned* __restrict__ codeR = g_code + (size_t)img * (NPIX / 4);
    unsigned* __restrict__ codeA = g_code + (size_t)(NIMG + img) * (NPIX / 4);

    #pragma unroll 4
    for (int it = 0; it < K1_CHUNK / (NTHREADS * 4); ++it) {
        const int pix = pbase + it * (NTHREADS * 4) + threadIdx.x * 4;
        const size_t off = ibase + (size_t)pix;

        float4 rl = __ldcs((const float4*)(rlab + off));
        float4 rp = __ldcs((const float4*)(rpre + off));
        float4 al = __ldcs((const float4*)(alab + off));
        float4 ap = __ldcs((const float4*)(apre + off));
        float4 mk = __ldcs((const float4*)(mask + off));

        int cr[4], ca[4];
        #define PROC(L, P, M, PC, PS, TS, CODE)                        \
        {   float d = (P) - (L);                                       \
            float l = d * d * (M);                                     \
            TS += l;                                                   \
            bool po = (L) > POS_THR;                                   \
            PC += po ? 1.f : 0.f;                                      \
            PS += po ? l   : 0.f;                                      \
            float nv = po ? 0.f : l;                                   \
            int c = __float2int_rn(sqrtf(nv) * QSCALE);                \
            CODE = min(c, 255); }

        PROC(rl.x, rp.x, mk.x, p_r, ps_r, ts_r, cr[0])
        PROC(rl.y, rp.y, mk.y, p_r, ps_r, ts_r, cr[1])
        PROC(rl.z, rp.z, mk.z, p_r, ps_r, ts_r, cr[2])
        PROC(rl.w, rp.w, mk.w, p_r, ps_r, ts_r, cr[3])
        PROC(al.x, ap.x, mk.x, p_a, ps_a, ts_a, ca[0])
        PROC(al.y, ap.y, mk.y, p_a, ps_a, ts_a, ca[1])
        PROC(al.z, ap.z, mk.z, p_a, ps_a, ts_a, ca[2])
        PROC(al.w, ap.w, mk.w, p_a, ps_a, ts_a, ca[3])
        #undef PROC

        unsigned wr = (unsigned)cr[0] | ((unsigned)cr[1] << 8) |
                      ((unsigned)cr[2] << 16) | ((unsigned)cr[3] << 24);
        unsigned wa = (unsigned)ca[0] | ((unsigned)ca[1] << 8) |
                      ((unsigned)ca[2] << 16) | ((unsigned)ca[3] << 24);
        codeR[pix >> 2] = wr;
        codeA[pix >> 2] = wa;

        if ((pix & 15) == 0) {  // every 16th pixel -> sample slot pix>>4
            g_scode[img * NSAMP + (pix >> 4)]          = (unsigned char)cr[0];
            g_scode[(NIMG + img) * NSAMP + (pix >> 4)] = (unsigned char)ca[0];
        }
    }

    // block reduce 6 stats -> atomicAdd
    __shared__ float sh[6][NTHREADS / 32];
    float vals[6] = {p_r, ps_r, ts_r, p_a, ps_a, ts_a};
    const int w = threadIdx.x >> 5, ln = threadIdx.x & 31;
    #pragma unroll
    for (int s = 0; s < 6; ++s) {
        float v = warp_sum(vals[s]);
        if (ln == 0) sh[s][w] = v;
    }
    __syncthreads();
    if (threadIdx.x < 6) {
        float v = 0.f;
        #pragma unroll
        for (int i = 0; i < NTHREADS / 32; ++i) v += sh[threadIdx.x][i];
        float* tgt;
        switch (threadIdx.x) {
            case 0: tgt = &g_p [img];        break;
            case 1: tgt = &g_ps[img];        break;
            case 2: tgt = &g_ts[img];        break;
            case 3: tgt = &g_p [NIMG + img]; break;
            case 4: tgt = &g_ps[NIMG + img]; break;
            default:tgt = &g_ts[NIMG + img]; break;
        }
        atomicAdd(tgt, v);
    }
}

// ---------------- k2: integer bisection on code samples ----------------
__global__ void __launch_bounds__(NTHREADS) k2_thresh(const int* __restrict__ neg_rto)
{
    const int ic = blockIdx.x;

    unsigned s[NSAMP / 4 / NTHREADS];   // 16 u32 = 64 sample codes per thread
    const unsigned* sp = ((const unsigned*)g_scode) + ic * (NSAMP / 4);
    #pragma unroll
    for (int i = 0; i < NSAMP / 4 / NTHREADS; ++i)
        s[i] = sp[threadIdx.x + NTHREADS * i];

    const float p    = g_p[ic];
    const float peff = (p > 0.f) ? p : FALLBACK_POS;
    const float kf   = (float)(*neg_rto) * peff;
    int k = (int)floorf(kf);
    int j = k >> 4;                       // target sample rank (NPIX/NSAMP = 16)
    if (j < 0) j = 0;
    if (j > NSAMP - 1) j = NSAMP - 1;

    __shared__ int s_lo, s_hi;
    __shared__ unsigned scnt[NTHREADS / 32];
    if (threadIdx.x == 0) { s_lo = -1; s_hi = 255; }
    __syncthreads();

    for (int iter = 0; iter < 8; ++iter) {
        const int mid = (s_lo + s_hi) >> 1;
        const unsigned mid4 = (unsigned)mid * 0x01010101u;
        unsigned c = 0;
        #pragma unroll
        for (int i = 0; i < NSAMP / 4 / NTHREADS; ++i) {
            unsigned m = __vcmpgtu4(s[i], mid4);
            c = __dp4a(m & 0x01010101u, 0x01010101u, c);
        }
        c = warp_sum_u(c);
        if ((threadIdx.x & 31) == 0) scnt[threadIdx.x >> 5] = c;
        __syncthreads();
        if (threadIdx.x == 0) {
            unsigned tot = 0;
            #pragma unroll
            for (int i = 0; i < NTHREADS / 32; ++i) tot += scnt[i];
            if ((int)tot > j) s_lo = mid; else s_hi = mid;
        }
        __syncthreads();
    }
    if (threadIdx.x == 0) g_ct[ic] = s_hi;
}

// ---------------- k3: exact C, sum(code^2) above code threshold ----------------
__global__ void __launch_bounds__(NTHREADS) k3_topsum()
{
    const int blk   = blockIdx.x;
    const int ic    = blk / K3_BPC;
    const int chunk = blk % K3_BPC;
    const unsigned ct4 = (unsigned)g_ct[ic] * 0x01010101u;
    // each block: NPIX/4/K3_BPC = 4096 u32 -> 16 u32/thread -> 4 uint4, fully unrolled
    const size_t base = (size_t)ic * (NPIX / 4) + (size_t)chunk * (NPIX / 4 / K3_BPC);

    unsigned cnt = 0, sc2 = 0;
    #pragma unroll
    for (int it = 0; it < (NPIX / 4 / K3_BPC) / (NTHREADS * 4); ++it) {  // 4 iters
        const size_t off = base + (size_t)it * (NTHREADS * 4) + threadIdx.x * 4;
        uint4 wv = __ldcs((const uint4*)(g_code + off));
        #define STEP(x)                                        \
        {   unsigned m  = __vcmpgtu4((x), ct4);                \
            unsigned sl = (x) & m;                             \
            sc2 = __dp4a(sl, sl, sc2);                         \
            cnt = __dp4a(m & 0x01010101u, 0x01010101u, cnt); }
        STEP(wv.x) STEP(wv.y) STEP(wv.z) STEP(wv.w)
        #undef STEP
    }

    __shared__ unsigned shC[NTHREADS / 32], shS[NTHREADS / 32];
    unsigned cv = warp_sum_u(cnt);
    unsigned sv = warp_sum_u(sc2);
    const int w = threadIdx.x >> 5, ln = threadIdx.x & 31;
    if (ln == 0) { shC[w] = cv; shS[w] = sv; }
    __syncthreads();
    if (threadIdx.x == 0) {
        unsigned cc = 0, ss = 0;
        #pragma unroll
        for (int i = 0; i < NTHREADS / 32; ++i) { cc += shC[i]; ss += shS[i]; }
        atomicAdd(&g_C[ic],  (float)cc);
        atomicAdd(&g_S2[ic], (float)ss);
    }
}

// ---------------- k4: assemble final scalar + re-zero state for next call ------
__global__ void __launch_bounds__(NIC) k4_final(const int* __restrict__ neg_rto,
                                                float* __restrict__ out)
{
    const int ic = threadIdx.x;
    float v;
    {
        const float p  = g_p[ic];
        const float ps = g_ps[ic];
        const float ts = g_ts[ic];
        const float C  = g_C[ic];
        const float S2 = g_S2[ic];
        const float ct = (float)g_ct[ic];
        const float n  = (float)NPIX - p;

        const float pos_loss = (p > 0.f) ? ps / fmaxf(p, 1.f) : 0.f;
        const float peff = (p > 0.f) ? p : FALLBACK_POS;
        const float kf   = (float)(*neg_rto) * peff;
        const float k    = floorf(kf);

        const float S    = S2 * (QSTEP * QSTEP);        // decoded sum of codes > ct
        const float tval = (ct * QSTEP) * (ct * QSTEP); // decoded threshold value

        float neg_loss;
        if ((p > 0.f) && (n < kf)) {
            neg_loss = (ts - ps) / fmaxf(n, 1.f);
        } else {
            neg_loss = (S + (k - C) * tval) / kf;
        }
        v = pos_loss + neg_loss;
    }

    // re-zero accumulators for the next invocation (statics are zero at load,
    // so call #1 is correct; this keeps every later call/replay correct too)
    g_p[ic] = 0.f; g_ps[ic] = 0.f; g_ts[ic] = 0.f;
    g_C[ic] = 0.f; g_S2[ic] = 0.f;

    __shared__ float sh[NIC];
    sh[ic] = v;
    __syncthreads();
    #pragma unroll
    for (int o = NIC / 2; o; o >>= 1) {
        if (ic < o) sh[ic] += sh[ic + o];
        __syncthreads();
    }
    if (ic == 0) out[0] = sh[0] / (float)NIMG;
}

// ---------------- launch ----------------
extern "C" void kernel_launch(void* const* d_in, const int* in_sizes, int n_in,
                              void* d_out, int out_size)
{
    const float* rlab = (const float*)d_in[0];
    const float* alab = (const float*)d_in[1];
    const float* rpre = (const float*)d_in[2];
    const float* apre = (const float*)d_in[3];
    const float* mask = (const float*)d_in[4];
    const int*   nrto = (const int*)  d_in[5];
    float* out = (float*)d_out;
    (void)in_sizes; (void)n_in; (void)out_size;

    k1_scan  <<<NIMG * K1_BPI, NTHREADS>>>(rlab, alab, rpre, apre, mask);
    k2_thresh<<<NIC, NTHREADS>>>(nrto);
    k3_topsum<<<NIC * K3_BPC, NTHREADS>>>();
    k4_final <<<1, NIC>>>(nrto, out);
}